// round 2
// baseline (speedup 1.0000x reference)
#include <cuda_runtime.h>
#include <cuda_bf16.h>
#include <cstdint>

// Problem constants (NeighborhoodSelfAttention: B=1, N=50000, K=16, D=128, H=8)
#define MAXN 50000
#define D 128
#define KNBR 16

// Scratch: device globals (no allocation allowed)
__device__ __align__(16) float g_Q[MAXN * D];
__device__ __align__(16) float g_K[MAXN * D];
__device__ __align__(16) float g_V[MAXN * D];
__device__ __align__(16) float g_att[MAXN * D];

// ---------------------------------------------------------------------------
// Packed f32x2 helpers (Blackwell FFMA2 path)
// ---------------------------------------------------------------------------
__device__ __forceinline__ void fma2(unsigned long long& d,
                                     unsigned long long a,
                                     unsigned long long b) {
    asm("fma.rn.f32x2 %0, %1, %2, %0;" : "+l"(d) : "l"(a), "l"(b));
}
__device__ __forceinline__ unsigned long long pack2(float x, float y) {
    unsigned long long r;
    asm("mov.b64 %0, {%1, %2};" : "=l"(r) : "f"(x), "f"(y));
    return r;
}
__device__ __forceinline__ void unpack2(unsigned long long v, float& x, float& y) {
    asm("mov.b64 {%0, %1}, %2;" : "=f"(x), "=f"(y) : "l"(v));
}

// ---------------------------------------------------------------------------
// Tiled GEMM body: Y[M,128] = X[M,128] @ W[128,128] + bias
// 256 threads, tile 128x128, K-chunks of 32, 8x8 micro-tile via f32x2 pairs.
// ---------------------------------------------------------------------------
#define TM 128
#define KB 32

__device__ __forceinline__ void gemm_body(const float* __restrict__ X,
                                          const float* __restrict__ W,
                                          const float* __restrict__ bias,
                                          float* __restrict__ Y, int M) {
    __shared__ float As[TM][KB + 1];   // +1 pad: conflict-free scalar a reads
    __shared__ float Bs[KB][D];

    const int tid = threadIdx.x;
    const int tx = tid & 15;           // 0..15 -> n groups of 8
    const int ty = tid >> 4;           // 0..15 -> m groups of 8
    const int m0 = blockIdx.x * TM;

    unsigned long long acc[8][4];
#pragma unroll
    for (int i = 0; i < 8; i++)
#pragma unroll
        for (int p = 0; p < 4; p++) acc[i][p] = 0ull;  // two packed +0.0f

    for (int kt = 0; kt < D; kt += KB) {
        // ---- load A tile: X[m0+r][kt..kt+31], 128 rows x 8 float4
        {
            int r  = tid >> 3;          // 0..31
            int c4 = (tid & 7) << 2;    // 0,4,..,28
#pragma unroll
            for (int i = 0; i < 4; i++) {
                int row = r + i * 32;
                int gm  = m0 + row;
                float4 v = make_float4(0.f, 0.f, 0.f, 0.f);
                if (gm < M)
                    v = *reinterpret_cast<const float4*>(
                        &X[(size_t)gm * D + kt + c4]);
                As[row][c4 + 0] = v.x;
                As[row][c4 + 1] = v.y;
                As[row][c4 + 2] = v.z;
                As[row][c4 + 3] = v.w;
            }
        }
        // ---- load B tile: W[kt+r][0..127], 32 rows x 32 float4
        {
            int r  = tid >> 5;          // 0..7
            int c4 = (tid & 31) << 2;   // 0,4,..,124
#pragma unroll
            for (int i = 0; i < 4; i++) {
                int row = r + i * 8;
                *reinterpret_cast<float4*>(&Bs[row][c4]) =
                    *reinterpret_cast<const float4*>(&W[(kt + row) * D + c4]);
            }
        }
        __syncthreads();

#pragma unroll 8
        for (int kk = 0; kk < KB; kk++) {
            const ulonglong2* brow =
                reinterpret_cast<const ulonglong2*>(&Bs[kk][0]);
            ulonglong2 b01 = brow[tx * 2];
            ulonglong2 b23 = brow[tx * 2 + 1];
            unsigned long long b[4] = {b01.x, b01.y, b23.x, b23.y};
#pragma unroll
            for (int i = 0; i < 8; i++) {
                float a = As[ty * 8 + i][kk];
                unsigned long long aa = pack2(a, a);
                fma2(acc[i][0], aa, b[0]);
                fma2(acc[i][1], aa, b[1]);
                fma2(acc[i][2], aa, b[2]);
                fma2(acc[i][3], aa, b[3]);
            }
        }
        __syncthreads();
    }

    // ---- epilogue
    const int n0 = tx * 8;
    float bv[8];
#pragma unroll
    for (int j = 0; j < 8; j++) bv[j] = bias[n0 + j];

#pragma unroll
    for (int i = 0; i < 8; i++) {
        int m = m0 + ty * 8 + i;
        if (m < M) {
            float o[8];
            unpack2(acc[i][0], o[0], o[1]);
            unpack2(acc[i][1], o[2], o[3]);
            unpack2(acc[i][2], o[4], o[5]);
            unpack2(acc[i][3], o[6], o[7]);
            float4 r0 = make_float4(o[0] + bv[0], o[1] + bv[1],
                                    o[2] + bv[2], o[3] + bv[3]);
            float4 r1 = make_float4(o[4] + bv[4], o[5] + bv[5],
                                    o[6] + bv[6], o[7] + bv[7]);
            *reinterpret_cast<float4*>(&Y[(size_t)m * D + n0])     = r0;
            *reinterpret_cast<float4*>(&Y[(size_t)m * D + n0 + 4]) = r1;
        }
    }
}

// Kernel A: fused QKV projection (grid.y picks Wq/Wk/Wv)
__global__ __launch_bounds__(256) void qkv_kernel(
    const float* __restrict__ X,
    const float* __restrict__ Wq, const float* __restrict__ bq,
    const float* __restrict__ Wk, const float* __restrict__ bk,
    const float* __restrict__ Wv, const float* __restrict__ bv, int M) {
    const float* W;
    const float* b;
    float* Y;
    if (blockIdx.y == 0)      { W = Wq; b = bq; Y = g_Q; }
    else if (blockIdx.y == 1) { W = Wk; b = bk; Y = g_K; }
    else                      { W = Wv; b = bv; Y = g_V; }
    gemm_body(X, W, b, Y, M);
}

// Kernel C: output projection
__global__ __launch_bounds__(256) void out_kernel(
    const float* __restrict__ Wo, const float* __restrict__ bo,
    float* __restrict__ Y, int M) {
    gemm_body(g_att, Wo, bo, Y, M);
}

// ---------------------------------------------------------------------------
// Kernel B: one warp per node. Gather 16 K rows + 16 V rows (L2-resident),
// per-head (16-dim) dots via shfl reduction, softmax, weighted V sum.
// NOTE: neighbors buffer is INT32 (JAX downgrades int64 without x64 mode).
// ---------------------------------------------------------------------------
__global__ __launch_bounds__(256) void attn_kernel(
    const int* __restrict__ nbrs, int N) {
    int warp = (blockIdx.x * blockDim.x + threadIdx.x) >> 5;
    if (warp >= N) return;
    int lane = threadIdx.x & 31;

    const float4* __restrict__ Qv = reinterpret_cast<const float4*>(g_Q);
    const float4* __restrict__ Kv = reinterpret_cast<const float4*>(g_K);
    const float4* __restrict__ Vv = reinterpret_cast<const float4*>(g_V);

    float4 q = Qv[warp * 32 + lane];   // dims [4*lane, 4*lane+4) ; head = lane/4

    float  s[KNBR];
    float4 vv[KNBR];

#pragma unroll
    for (int j = 0; j < KNBR; j++) {
        int nb  = __ldg(&nbrs[(size_t)warp * KNBR + j]);
        int idx = nb >= 0 ? nb : 0;               // clip(neighbors, 0)
        if (idx >= N) idx = 0;                    // safety clamp
        float4 k4 = Kv[idx * 32 + lane];
        vv[j]     = Vv[idx * 32 + lane];
        float p = q.x * k4.x + q.y * k4.y + q.z * k4.z + q.w * k4.w;
        p += __shfl_xor_sync(0xffffffffu, p, 1);
        p += __shfl_xor_sync(0xffffffffu, p, 2);  // full 16-dim head dot
        s[j] = (nb >= 0) ? p * 0.25f : -1.0e9f;   // scale = 1/sqrt(16)
    }

    float m = -3.0e38f;
#pragma unroll
    for (int j = 0; j < KNBR; j++) m = fmaxf(m, s[j]);
    float sum = 0.f;
#pragma unroll
    for (int j = 0; j < KNBR; j++) {
        float e = __expf(s[j] - m);
        s[j] = e;
        sum += e;
    }
    float inv = 1.f / sum;

    float4 acc = make_float4(0.f, 0.f, 0.f, 0.f);
#pragma unroll
    for (int j = 0; j < KNBR; j++) {
        float w = s[j] * inv;
        acc.x += w * vv[j].x;
        acc.y += w * vv[j].y;
        acc.z += w * vv[j].z;
        acc.w += w * vv[j].w;
    }
    reinterpret_cast<float4*>(g_att)[warp * 32 + lane] = acc;
}

// ---------------------------------------------------------------------------
// Launch: A (QKV) -> B (attention) -> C (output proj), all default stream.
// Inputs: x, neighbors, Wq, bq, Wk, bk, Wv, bv, Wo, bo
// ---------------------------------------------------------------------------
extern "C" void kernel_launch(void* const* d_in, const int* in_sizes, int n_in,
                              void* d_out, int out_size) {
    const float* x    = (const float*)d_in[0];
    const int*   nbrs = (const int*)d_in[1];
    const float* Wq   = (const float*)d_in[2];
    const float* bq   = (const float*)d_in[3];
    const float* Wk   = (const float*)d_in[4];
    const float* bk   = (const float*)d_in[5];
    const float* Wv   = (const float*)d_in[6];
    const float* bv   = (const float*)d_in[7];
    const float* Wo   = (const float*)d_in[8];
    const float* bo   = (const float*)d_in[9];
    float*       out  = (float*)d_out;

    int N = in_sizes[0] / D;   // 50000

    dim3 gA((N + TM - 1) / TM, 3);
    qkv_kernel<<<gA, 256>>>(x, Wq, bq, Wk, bk, Wv, bv, N);

    int blocksB = (N + 7) / 8;  // 8 warps / block
    attn_kernel<<<blocksB, 256>>>(nbrs, N);

    dim3 gC((N + TM - 1) / TM, 1);
    out_kernel<<<gC, 256>>>(Wo, bo, out, N);
}

// round 5
// speedup vs baseline: 1.2676x; 1.2676x over previous
#include <cuda_runtime.h>
#include <cuda_fp16.h>
#include <cstdint>

// Problem constants (NeighborhoodSelfAttention: B=1, N=50000, K=16, D=128, H=8)
#define MAXN 50000
#define D 128
#define KNBR 16

// Scratch: device globals (no allocation allowed)
__device__ __align__(16) float  g_Q[MAXN * D];
__device__ __align__(16) __half g_Kh[MAXN * D];
__device__ __align__(16) __half g_Vh[MAXN * D];
__device__ __align__(16) float  g_att[MAXN * D];

// ---------------------------------------------------------------------------
// Packed f32x2 helpers (Blackwell FFMA2 path)
// ---------------------------------------------------------------------------
__device__ __forceinline__ void fma2(unsigned long long& d,
                                     unsigned long long a,
                                     unsigned long long b) {
    asm("fma.rn.f32x2 %0, %1, %2, %0;" : "+l"(d) : "l"(a), "l"(b));
}
__device__ __forceinline__ unsigned long long pack2(float x, float y) {
    unsigned long long r;
    asm("mov.b64 %0, {%1, %2};" : "=l"(r) : "f"(x), "f"(y));
    return r;
}
__device__ __forceinline__ void unpack2(unsigned long long v, float& x, float& y) {
    asm("mov.b64 {%0, %1}, %2;" : "=f"(x), "=f"(y) : "l"(v));
}

// ---------------------------------------------------------------------------
// Tiled GEMM body: Y[M,128] = X[M,128] @ W[128,128] + bias
// 256 threads, tile 128x128, K-chunks of 32, 8x8 micro-tile via f32x2 pairs.
// Shared tiles passed in (single buffer per kernel across instantiations).
// OUT_FP16: write result as fp16 (for K/V); else fp32.
// ---------------------------------------------------------------------------
#define TM 128
#define KB 32
#define AS_LD (KB + 1)

struct SmemTiles {
    float As[TM][AS_LD];
    float Bs[KB][D];
};

template <bool OUT_FP16>
__device__ __forceinline__ void gemm_body(SmemTiles* sm,
                                          const float* __restrict__ X,
                                          const float* __restrict__ W,
                                          const float* __restrict__ bias,
                                          float* __restrict__ Yf,
                                          __half* __restrict__ Yh,
                                          int M) {
    float (*As)[AS_LD] = sm->As;
    float (*Bs)[D]     = sm->Bs;

    const int tid = threadIdx.x;
    const int tx = tid & 15;           // 0..15 -> n groups of 8
    const int ty = tid >> 4;           // 0..15 -> m groups of 8
    const int m0 = blockIdx.x * TM;

    unsigned long long acc[8][4];
#pragma unroll
    for (int i = 0; i < 8; i++)
#pragma unroll
        for (int p = 0; p < 4; p++) acc[i][p] = 0ull;  // two packed +0.0f

    for (int kt = 0; kt < D; kt += KB) {
        // ---- load A tile: X[m0+r][kt..kt+31], 128 rows x 8 float4
        {
            int r  = tid >> 3;          // 0..31
            int c4 = (tid & 7) << 2;    // 0,4,..,28
#pragma unroll
            for (int i = 0; i < 4; i++) {
                int row = r + i * 32;
                int gm  = m0 + row;
                float4 v = make_float4(0.f, 0.f, 0.f, 0.f);
                if (gm < M)
                    v = *reinterpret_cast<const float4*>(
                        &X[(size_t)gm * D + kt + c4]);
                As[row][c4 + 0] = v.x;
                As[row][c4 + 1] = v.y;
                As[row][c4 + 2] = v.z;
                As[row][c4 + 3] = v.w;
            }
        }
        // ---- load B tile: W[kt+r][0..127], 32 rows x 32 float4
        {
            int r  = tid >> 5;          // 0..7
            int c4 = (tid & 31) << 2;   // 0,4,..,124
#pragma unroll
            for (int i = 0; i < 4; i++) {
                int row = r + i * 8;
                *reinterpret_cast<float4*>(&Bs[row][c4]) =
                    *reinterpret_cast<const float4*>(&W[(kt + row) * D + c4]);
            }
        }
        __syncthreads();

#pragma unroll 8
        for (int kk = 0; kk < KB; kk++) {
            const ulonglong2* brow =
                reinterpret_cast<const ulonglong2*>(&Bs[kk][0]);
            ulonglong2 b01 = brow[tx * 2];
            ulonglong2 b23 = brow[tx * 2 + 1];
#pragma unroll
            for (int i = 0; i < 8; i++) {
                float a = As[ty * 8 + i][kk];
                unsigned long long aa = pack2(a, a);
                fma2(acc[i][0], aa, b01.x);
                fma2(acc[i][1], aa, b01.y);
                fma2(acc[i][2], aa, b23.x);
                fma2(acc[i][3], aa, b23.y);
            }
        }
        __syncthreads();
    }

    // ---- epilogue
    const int n0 = tx * 8;
    float bv[8];
#pragma unroll
    for (int j = 0; j < 8; j++) bv[j] = bias[n0 + j];

#pragma unroll
    for (int i = 0; i < 8; i++) {
        int m = m0 + ty * 8 + i;
        if (m < M) {
            float o[8];
            unpack2(acc[i][0], o[0], o[1]);
            unpack2(acc[i][1], o[2], o[3]);
            unpack2(acc[i][2], o[4], o[5]);
            unpack2(acc[i][3], o[6], o[7]);
#pragma unroll
            for (int j = 0; j < 8; j++) o[j] += bv[j];
            if (OUT_FP16) {
                uint4 pk;
                __half2 h0 = __floats2half2_rn(o[0], o[1]);
                __half2 h1 = __floats2half2_rn(o[2], o[3]);
                __half2 h2 = __floats2half2_rn(o[4], o[5]);
                __half2 h3 = __floats2half2_rn(o[6], o[7]);
                pk.x = *reinterpret_cast<unsigned*>(&h0);
                pk.y = *reinterpret_cast<unsigned*>(&h1);
                pk.z = *reinterpret_cast<unsigned*>(&h2);
                pk.w = *reinterpret_cast<unsigned*>(&h3);
                *reinterpret_cast<uint4*>(&Yh[(size_t)m * D + n0]) = pk;
            } else {
                float4 r0 = make_float4(o[0], o[1], o[2], o[3]);
                float4 r1 = make_float4(o[4], o[5], o[6], o[7]);
                *reinterpret_cast<float4*>(&Yf[(size_t)m * D + n0])     = r0;
                *reinterpret_cast<float4*>(&Yf[(size_t)m * D + n0 + 4]) = r1;
            }
        }
    }
}

// Kernel A: fused QKV projection (grid.y picks Wq/Wk/Wv).
// Q written fp32; K,V written fp16 (halves the attention gather traffic;
// fp16 not bf16 — bf16's 8-bit mantissa gave rel_err 1.66e-3 > 1e-3 gate).
__global__ __launch_bounds__(256, 2) void qkv_kernel(
    const float* __restrict__ X,
    const float* __restrict__ Wq, const float* __restrict__ bq,
    const float* __restrict__ Wk, const float* __restrict__ bk,
    const float* __restrict__ Wv, const float* __restrict__ bv, int M) {
    __shared__ SmemTiles sm;
    if (blockIdx.y == 0)
        gemm_body<false>(&sm, X, Wq, bq, g_Q, nullptr, M);
    else if (blockIdx.y == 1)
        gemm_body<true>(&sm, X, Wk, bk, nullptr, g_Kh, M);
    else
        gemm_body<true>(&sm, X, Wv, bv, nullptr, g_Vh, M);
}

// Kernel C: output projection (fp32 in/out)
__global__ __launch_bounds__(256, 2) void out_kernel(
    const float* __restrict__ Wo, const float* __restrict__ bo,
    float* __restrict__ Y, int M) {
    __shared__ SmemTiles sm;
    gemm_body<false>(&sm, g_att, Wo, bo, Y, nullptr, M);
}

// ---------------------------------------------------------------------------
// Kernel B: one warp per node. Gather 16 K rows + 16 V rows in fp16
// (L2-resident), per-head (16-dim) dots via shfl reduction, softmax,
// weighted V sum. neighbors buffer is INT32.
// ---------------------------------------------------------------------------
__global__ __launch_bounds__(256) void attn_kernel(
    const int* __restrict__ nbrs, int N) {
    int warp = (blockIdx.x * blockDim.x + threadIdx.x) >> 5;
    if (warp >= N) return;
    int lane = threadIdx.x & 31;

    const float4* __restrict__ Qv = reinterpret_cast<const float4*>(g_Q);
    const uint2*  __restrict__ Kh = reinterpret_cast<const uint2*>(g_Kh);
    const uint2*  __restrict__ Vh = reinterpret_cast<const uint2*>(g_Vh);

    float4 q = Qv[warp * 32 + lane];   // dims [4*lane, 4*lane+4) ; head = lane/4

    float s[KNBR];
    uint2 vraw[KNBR];

#pragma unroll
    for (int j = 0; j < KNBR; j++) {
        int nb  = __ldg(&nbrs[(size_t)warp * KNBR + j]);
        int idx = nb >= 0 ? nb : 0;               // clip(neighbors, 0)
        if (idx >= N) idx = 0;                    // safety clamp
        uint2 kr = Kh[idx * 32 + lane];           // 4 fp16 (row is 32 uint2)
        vraw[j]  = Vh[idx * 32 + lane];
        float2 k0 = __half22float2(*reinterpret_cast<__half2*>(&kr.x));
        float2 k1 = __half22float2(*reinterpret_cast<__half2*>(&kr.y));
        float p = q.x * k0.x + q.y * k0.y + q.z * k1.x + q.w * k1.y;
        p += __shfl_xor_sync(0xffffffffu, p, 1);
        p += __shfl_xor_sync(0xffffffffu, p, 2);  // full 16-dim head dot
        s[j] = (nb >= 0) ? p * 0.25f : -1.0e9f;   // scale = 1/sqrt(16)
    }

    float m = -3.0e38f;
#pragma unroll
    for (int j = 0; j < KNBR; j++) m = fmaxf(m, s[j]);
    float sum = 0.f;
#pragma unroll
    for (int j = 0; j < KNBR; j++) {
        float e = __expf(s[j] - m);
        s[j] = e;
        sum += e;
    }
    float inv = 1.f / sum;

    float4 acc = make_float4(0.f, 0.f, 0.f, 0.f);
#pragma unroll
    for (int j = 0; j < KNBR; j++) {
        float w = s[j] * inv;
        float2 v0 = __half22float2(*reinterpret_cast<__half2*>(&vraw[j].x));
        float2 v1 = __half22float2(*reinterpret_cast<__half2*>(&vraw[j].y));
        acc.x += w * v0.x;
        acc.y += w * v0.y;
        acc.z += w * v1.x;
        acc.w += w * v1.y;
    }
    reinterpret_cast<float4*>(g_att)[warp * 32 + lane] = acc;
}

// ---------------------------------------------------------------------------
// Launch: A (QKV) -> B (attention) -> C (output proj), all default stream.
// Inputs: x, neighbors, Wq, bq, Wk, bk, Wv, bv, Wo, bo
// ---------------------------------------------------------------------------
extern "C" void kernel_launch(void* const* d_in, const int* in_sizes, int n_in,
                              void* d_out, int out_size) {
    const float* x    = (const float*)d_in[0];
    const int*   nbrs = (const int*)d_in[1];
    const float* Wq   = (const float*)d_in[2];
    const float* bq   = (const float*)d_in[3];
    const float* Wk   = (const float*)d_in[4];
    const float* bk   = (const float*)d_in[5];
    const float* Wv   = (const float*)d_in[6];
    const float* bv   = (const float*)d_in[7];
    const float* Wo   = (const float*)d_in[8];
    const float* bo   = (const float*)d_in[9];
    float*       out  = (float*)d_out;

    int N = in_sizes[0] / D;   // 50000

    dim3 gA((N + TM - 1) / TM, 3);
    qkv_kernel<<<gA, 256>>>(x, Wq, bq, Wk, bk, Wv, bv, N);

    int blocksB = (N + 7) / 8;  // 8 warps / block
    attn_kernel<<<blocksB, 256>>>(nbrs, N);

    dim3 gC((N + TM - 1) / TM, 1);
    out_kernel<<<gC, 256>>>(Wo, bo, out, N);
}

// round 6
// speedup vs baseline: 2.8049x; 2.2128x over previous
#include <cuda_runtime.h>
#include <cuda_fp16.h>
#include <cstdint>

// Problem constants (NeighborhoodSelfAttention: B=1, N=50000, K=16, D=128, H=8)
#define MAXN 50000
#define D 128
#define KNBR 16

// Scratch: device globals (no allocation allowed). All intermediates fp16.
__device__ __align__(16) __half g_Q[MAXN * D];
__device__ __align__(16) __half g_K[MAXN * D];
__device__ __align__(16) __half g_V[MAXN * D];
__device__ __align__(16) __half g_att[MAXN * D];

// ---------------------------------------------------------------------------
// Tensor-core GEMM: Y[M,128] = X[M,128] @ W[128,128] + bias
// fp16 inputs (converted on load), fp32 accumulate via mma.sync.m16n8k16.
// 256 threads, tile 128x128, K in two 64-steps. 8 warps of 64x32 tiles.
// ---------------------------------------------------------------------------
#define TM 128
#define KSTEP 64
#define A_LD 72    // 64 + 8 halves pad -> 36-word row stride (conflict-free ldmatrix)
#define B_LD 136   // 128 + 8 halves pad -> 68-word row stride

struct GemmSmem {
    __half A[TM][A_LD];     // A tile [m][k]
    __half B[KSTEP][B_LD];  // W tile [k][n] (natural layout, ldmatrix.trans)
};

__device__ __forceinline__ uint32_t smem_u32(const void* p) {
    return (uint32_t)__cvta_generic_to_shared(p);
}
__device__ __forceinline__ void ldsm_x4(uint32_t& r0, uint32_t& r1,
                                        uint32_t& r2, uint32_t& r3,
                                        uint32_t addr) {
    asm volatile("ldmatrix.sync.aligned.m8n8.x4.shared.b16 {%0,%1,%2,%3}, [%4];"
                 : "=r"(r0), "=r"(r1), "=r"(r2), "=r"(r3) : "r"(addr));
}
__device__ __forceinline__ void ldsm_x2t(uint32_t& r0, uint32_t& r1,
                                         uint32_t addr) {
    asm volatile("ldmatrix.sync.aligned.m8n8.x2.trans.shared.b16 {%0,%1}, [%2];"
                 : "=r"(r0), "=r"(r1) : "r"(addr));
}
__device__ __forceinline__ void mma16816(float& c0, float& c1, float& c2, float& c3,
                                         uint32_t a0, uint32_t a1, uint32_t a2,
                                         uint32_t a3, uint32_t b0, uint32_t b1) {
    asm volatile(
        "mma.sync.aligned.m16n8k16.row.col.f32.f16.f16.f32 "
        "{%0,%1,%2,%3}, {%4,%5,%6,%7}, {%8,%9}, {%0,%1,%2,%3};"
        : "+f"(c0), "+f"(c1), "+f"(c2), "+f"(c3)
        : "r"(a0), "r"(a1), "r"(a2), "r"(a3), "r"(b0), "r"(b1));
}

// A_FP16: A matrix already fp16 in gmem (g_att); else fp32 converted on load.
// OUT_FP32: write fp32 (final output); else fp16.
template <bool A_FP16, bool OUT_FP32>
__device__ __forceinline__ void hgemm(GemmSmem* sm,
                                      const float* __restrict__ Af,
                                      const __half* __restrict__ Ah,
                                      const float* __restrict__ W,
                                      const float* __restrict__ bias,
                                      float* __restrict__ Yf,
                                      __half* __restrict__ Yh, int M) {
    const int tid  = threadIdx.x;
    const int lane = tid & 31;
    const int wid  = tid >> 5;
    const int m0   = blockIdx.x * TM;
    const int wm   = (wid >> 2) * 64;  // warp m-base: 0 or 64
    const int wn   = (wid & 3) * 32;   // warp n-base: 0..96

    float c[4][4][4];
#pragma unroll
    for (int mi = 0; mi < 4; mi++)
#pragma unroll
        for (int nj = 0; nj < 4; nj++)
#pragma unroll
            for (int r = 0; r < 4; r++) c[mi][nj][r] = 0.f;

    for (int k0 = 0; k0 < D; k0 += KSTEP) {
        // ---- stage A tile [128][64] as fp16
#pragma unroll
        for (int i = 0; i < 8; i++) {
            int lin = tid + i * 256;
            int row = lin >> 4;
            int col = (lin & 15) << 2;
            int gm  = m0 + row;
            uint2 pk = make_uint2(0u, 0u);
            if (A_FP16) {
                if (gm < M)
                    pk = *reinterpret_cast<const uint2*>(
                        &Ah[(size_t)gm * D + k0 + col]);
            } else {
                float4 v = make_float4(0.f, 0.f, 0.f, 0.f);
                if (gm < M)
                    v = *reinterpret_cast<const float4*>(
                        &Af[(size_t)gm * D + k0 + col]);
                __half2 h0 = __floats2half2_rn(v.x, v.y);
                __half2 h1 = __floats2half2_rn(v.z, v.w);
                pk.x = *reinterpret_cast<unsigned*>(&h0);
                pk.y = *reinterpret_cast<unsigned*>(&h1);
            }
            *reinterpret_cast<uint2*>(&sm->A[row][col]) = pk;
        }
        // ---- stage B tile: W rows k0..k0+63, all 128 cols, as fp16
#pragma unroll
        for (int i = 0; i < 8; i++) {
            int lin = tid + i * 256;
            int row = lin >> 5;
            int col = (lin & 31) << 2;
            float4 v = *reinterpret_cast<const float4*>(
                &W[(size_t)(k0 + row) * D + col]);
            __half2 h0 = __floats2half2_rn(v.x, v.y);
            __half2 h1 = __floats2half2_rn(v.z, v.w);
            uint2 pk;
            pk.x = *reinterpret_cast<unsigned*>(&h0);
            pk.y = *reinterpret_cast<unsigned*>(&h1);
            *reinterpret_cast<uint2*>(&sm->B[row][col]) = pk;
        }
        __syncthreads();

#pragma unroll
        for (int kk = 0; kk < KSTEP; kk += 16) {
            uint32_t a[4][4], b[4][2];
#pragma unroll
            for (int mi = 0; mi < 4; mi++) {
                uint32_t addr = smem_u32(
                    &sm->A[wm + mi * 16 + (lane & 15)][kk + ((lane >> 4) << 3)]);
                ldsm_x4(a[mi][0], a[mi][1], a[mi][2], a[mi][3], addr);
            }
#pragma unroll
            for (int nj = 0; nj < 4; nj++) {
                uint32_t addr = smem_u32(&sm->B[kk + (lane & 15)][wn + nj * 8]);
                ldsm_x2t(b[nj][0], b[nj][1], addr);
            }
#pragma unroll
            for (int mi = 0; mi < 4; mi++)
#pragma unroll
                for (int nj = 0; nj < 4; nj++)
                    mma16816(c[mi][nj][0], c[mi][nj][1], c[mi][nj][2], c[mi][nj][3],
                             a[mi][0], a[mi][1], a[mi][2], a[mi][3],
                             b[nj][0], b[nj][1]);
        }
        __syncthreads();
    }

    // ---- epilogue: add bias, store
#pragma unroll
    for (int mi = 0; mi < 4; mi++) {
        int r0 = m0 + wm + mi * 16 + (lane >> 2);
#pragma unroll
        for (int nj = 0; nj < 4; nj++) {
            int col  = wn + nj * 8 + ((lane & 3) << 1);
            float b0 = bias[col], b1 = bias[col + 1];
            float v00 = c[mi][nj][0] + b0, v01 = c[mi][nj][1] + b1;
            float v10 = c[mi][nj][2] + b0, v11 = c[mi][nj][3] + b1;
            if (r0 < M) {
                if (OUT_FP32) {
                    *reinterpret_cast<float2*>(&Yf[(size_t)r0 * D + col]) =
                        make_float2(v00, v01);
                } else {
                    __half2 h = __floats2half2_rn(v00, v01);
                    *reinterpret_cast<unsigned*>(&Yh[(size_t)r0 * D + col]) =
                        *reinterpret_cast<unsigned*>(&h);
                }
            }
            if (r0 + 8 < M) {
                if (OUT_FP32) {
                    *reinterpret_cast<float2*>(&Yf[(size_t)(r0 + 8) * D + col]) =
                        make_float2(v10, v11);
                } else {
                    __half2 h = __floats2half2_rn(v10, v11);
                    *reinterpret_cast<unsigned*>(&Yh[(size_t)(r0 + 8) * D + col]) =
                        *reinterpret_cast<unsigned*>(&h);
                }
            }
        }
    }
}

// Kernel A: fused QKV projection (grid.y picks Wq/Wk/Wv); all outputs fp16.
__global__ __launch_bounds__(256, 2) void qkv_kernel(
    const float* __restrict__ X,
    const float* __restrict__ Wq, const float* __restrict__ bq,
    const float* __restrict__ Wk, const float* __restrict__ bk,
    const float* __restrict__ Wv, const float* __restrict__ bv, int M) {
    __shared__ GemmSmem sm;
    if (blockIdx.y == 0)
        hgemm<false, false>(&sm, X, nullptr, Wq, bq, nullptr, g_Q, M);
    else if (blockIdx.y == 1)
        hgemm<false, false>(&sm, X, nullptr, Wk, bk, nullptr, g_K, M);
    else
        hgemm<false, false>(&sm, X, nullptr, Wv, bv, nullptr, g_V, M);
}

// Kernel C: output projection; A = g_att (fp16), output fp32.
__global__ __launch_bounds__(256, 2) void out_kernel(
    const float* __restrict__ Wo, const float* __restrict__ bo,
    float* __restrict__ Y, int M) {
    __shared__ GemmSmem sm;
    hgemm<true, true>(&sm, nullptr, g_att, Wo, bo, Y, nullptr, M);
}

// ---------------------------------------------------------------------------
// Kernel B: one warp per node. Gather 16 K + 16 V rows in fp16 (L2-resident),
// per-head (16-dim) dots via shfl, softmax, weighted V sum. nbrs is INT32.
// ---------------------------------------------------------------------------
__global__ __launch_bounds__(256) void attn_kernel(
    const int* __restrict__ nbrs, int N) {
    int warp = (blockIdx.x * blockDim.x + threadIdx.x) >> 5;
    if (warp >= N) return;
    int lane = threadIdx.x & 31;

    const uint2* __restrict__ Qh = reinterpret_cast<const uint2*>(g_Q);
    const uint2* __restrict__ Kh = reinterpret_cast<const uint2*>(g_K);
    const uint2* __restrict__ Vh = reinterpret_cast<const uint2*>(g_V);

    uint2 qr = Qh[warp * 32 + lane];   // 4 fp16: dims [4*lane,4*lane+4); head=lane/4
    float2 q0 = __half22float2(*reinterpret_cast<__half2*>(&qr.x));
    float2 q1 = __half22float2(*reinterpret_cast<__half2*>(&qr.y));

    float s[KNBR];
    uint2 vraw[KNBR];

#pragma unroll
    for (int j = 0; j < KNBR; j++) {
        int nb  = __ldg(&nbrs[(size_t)warp * KNBR + j]);
        int idx = nb >= 0 ? nb : 0;               // clip(neighbors, 0)
        if (idx >= N) idx = 0;                    // safety clamp
        uint2 kr = Kh[idx * 32 + lane];
        vraw[j]  = Vh[idx * 32 + lane];
        float2 k0 = __half22float2(*reinterpret_cast<__half2*>(&kr.x));
        float2 k1 = __half22float2(*reinterpret_cast<__half2*>(&kr.y));
        float p = q0.x * k0.x + q0.y * k0.y + q1.x * k1.x + q1.y * k1.y;
        p += __shfl_xor_sync(0xffffffffu, p, 1);
        p += __shfl_xor_sync(0xffffffffu, p, 2);  // full 16-dim head dot
        s[j] = (nb >= 0) ? p * 0.25f : -1.0e9f;   // scale = 1/sqrt(16)
    }

    float m = -3.0e38f;
#pragma unroll
    for (int j = 0; j < KNBR; j++) m = fmaxf(m, s[j]);
    float sum = 0.f;
#pragma unroll
    for (int j = 0; j < KNBR; j++) {
        float e = __expf(s[j] - m);
        s[j] = e;
        sum += e;
    }
    float inv = 1.f / sum;

    float4 acc = make_float4(0.f, 0.f, 0.f, 0.f);
#pragma unroll
    for (int j = 0; j < KNBR; j++) {
        float w = s[j] * inv;
        float2 v0 = __half22float2(*reinterpret_cast<__half2*>(&vraw[j].x));
        float2 v1 = __half22float2(*reinterpret_cast<__half2*>(&vraw[j].y));
        acc.x += w * v0.x;
        acc.y += w * v0.y;
        acc.z += w * v1.x;
        acc.w += w * v1.y;
    }
    __half2 o0 = __floats2half2_rn(acc.x, acc.y);
    __half2 o1 = __floats2half2_rn(acc.z, acc.w);
    uint2 pk;
    pk.x = *reinterpret_cast<unsigned*>(&o0);
    pk.y = *reinterpret_cast<unsigned*>(&o1);
    reinterpret_cast<uint2*>(g_att)[warp * 32 + lane] = pk;
}

// ---------------------------------------------------------------------------
// Launch: A (QKV) -> B (attention) -> C (output proj), all default stream.
// Inputs: x, neighbors, Wq, bq, Wk, bk, Wv, bv, Wo, bo
// ---------------------------------------------------------------------------
extern "C" void kernel_launch(void* const* d_in, const int* in_sizes, int n_in,
                              void* d_out, int out_size) {
    const float* x    = (const float*)d_in[0];
    const int*   nbrs = (const int*)d_in[1];
    const float* Wq   = (const float*)d_in[2];
    const float* bq   = (const float*)d_in[3];
    const float* Wk   = (const float*)d_in[4];
    const float* bk   = (const float*)d_in[5];
    const float* Wv   = (const float*)d_in[6];
    const float* bv   = (const float*)d_in[7];
    const float* Wo   = (const float*)d_in[8];
    const float* bo   = (const float*)d_in[9];
    float*       out  = (float*)d_out;

    int N = in_sizes[0] / D;   // 50000

    dim3 gA((N + TM - 1) / TM, 3);
    qkv_kernel<<<gA, 256>>>(x, Wq, bq, Wk, bk, Wv, bv, N);

    int blocksB = (N + 7) / 8;  // 8 warps / block
    attn_kernel<<<blocksB, 256>>>(nbrs, N);

    dim3 gC((N + TM - 1) / TM, 1);
    out_kernel<<<gC, 256>>>(Wo, bo, out, N);
}